// round 8
// baseline (speedup 1.0000x reference)
#include <cuda_runtime.h>
#include <cuda_bf16.h>
#include <stdint.h>
#include <math.h>

#define EPSV 1e-8f
#define DD 512
#define MR 8192
#define NR 8192
#define BM 128
#define BN 256
#define BK 64            // bf16 elements per pipeline step
#define PADK 72          // padded smem row (144 B) -> conflict-free ldmatrix
#define STAGES 3
#define SSTEPS 24        // 3 passes (hh, hl, lh) x 8 steps of K=64

// ---------------- device scratch (allocation-free) ----------------
__device__ __nv_bfloat16 g_ah[(size_t)MR * DD];
__device__ __nv_bfloat16 g_al[(size_t)MR * DD];
__device__ __nv_bfloat16 g_bh[(size_t)NR * DD];
__device__ __nv_bfloat16 g_bl[(size_t)NR * DD];
__device__ float g_na[MR];
__device__ float g_nb[NR];

__device__ __forceinline__ uint32_t smem_u32(const void* p) {
    uint32_t a;
    asm("{ .reg .u64 t; cvta.to.shared.u64 t, %1; cvt.u32.u64 %0, t; }" : "=r"(a) : "l"(p));
    return a;
}

#define CP16(dst, src) \
    asm volatile("cp.async.cg.shared.global [%0], [%1], 16;" :: "r"(dst), "l"(src))
#define CP_COMMIT() asm volatile("cp.async.commit_group;" ::: "memory")
#define CP_WAIT(n)  asm volatile("cp.async.wait_group %0;" :: "n"(n) : "memory")

#define LDSM_X4(r0, r1, r2, r3, addr) \
    asm volatile("ldmatrix.sync.aligned.m8n8.x4.shared.b16 {%0,%1,%2,%3}, [%4];" \
                 : "=r"(r0), "=r"(r1), "=r"(r2), "=r"(r3) : "r"(addr))

#define MMA16816(d, a, b0, b1) \
    asm volatile("mma.sync.aligned.m16n8k16.row.col.f32.bf16.bf16.f32 " \
                 "{%0,%1,%2,%3}, {%4,%5,%6,%7}, {%8,%9}, {%0,%1,%2,%3};" \
                 : "+f"((d)[0]), "+f"((d)[1]), "+f"((d)[2]), "+f"((d)[3]) \
                 : "r"((a)[0]), "r"((a)[1]), "r"((a)[2]), "r"((a)[3]), "r"(b0), "r"(b1))

// ---------------- prep: fp32 -> bf16 hi/lo + row norms ----------------
__global__ void prep_kernel(const float* __restrict__ x1, const float* __restrict__ x2) {
    int r = blockIdx.x;
    const float* src;
    __nv_bfloat16 *hi, *lo;
    float* nrm;
    int row;
    if (r < NR) { src = x1; hi = g_bh; lo = g_bl; nrm = g_nb; row = r; }
    else        { src = x2; hi = g_ah; lo = g_al; nrm = g_na; row = r - NR; }

    const float4* p = reinterpret_cast<const float4*>(src + (size_t)row * DD);
    float4 v = p[threadIdx.x];
    float vv[4] = {v.x, v.y, v.z, v.w};
    float s = v.x * v.x + v.y * v.y + v.z * v.z + v.w * v.w;

    __nv_bfloat16 h[4], l[4];
#pragma unroll
    for (int i = 0; i < 4; i++) {
        h[i] = __float2bfloat16(vv[i]);
        l[i] = __float2bfloat16(vv[i] - __bfloat162float(h[i]));
    }
    size_t o = (size_t)row * DD + threadIdx.x * 4;
    *reinterpret_cast<__nv_bfloat162*>(hi + o)     = __halves2bfloat162(h[0], h[1]);
    *reinterpret_cast<__nv_bfloat162*>(hi + o + 2) = __halves2bfloat162(h[2], h[3]);
    *reinterpret_cast<__nv_bfloat162*>(lo + o)     = __halves2bfloat162(l[0], l[1]);
    *reinterpret_cast<__nv_bfloat162*>(lo + o + 2) = __halves2bfloat162(l[2], l[3]);

#pragma unroll
    for (int off = 16; off > 0; off >>= 1)
        s += __shfl_down_sync(0xffffffffu, s, off);
    __shared__ float ws[4];
    if ((threadIdx.x & 31) == 0) ws[threadIdx.x >> 5] = s;
    __syncthreads();
    if (threadIdx.x == 0)
        nrm[row] = sqrtf(ws[0] + ws[1] + ws[2] + ws[3]);
}

// ---------------- GEMM via mma.sync + cosine epilogue ----------------
// Dynamic smem: STAGES stages, each [BM][PADK] A + [BN][PADK] B bf16.
#define STAGE_ELEMS ((BM + BN) * PADK)

__device__ __forceinline__ void load_stage(uint32_t sbase, int stage, int s,
                                           int bm, int bn, int tid) {
    const int pass = s >> 3;            // 0: hh, 1: hl, 2: lh
    const int ko = (s & 7) * BK;
    const __nv_bfloat16* Ap = (pass == 2) ? g_al : g_ah;
    const __nv_bfloat16* Bp = (pass == 1) ? g_bl : g_bh;
    uint32_t abase = sbase + stage * STAGE_ELEMS * 2;
    uint32_t bbase = abase + BM * PADK * 2;
    // A: 128 rows x 128 B = 1024 x 16B chunks (4/thread)
#pragma unroll
    for (int h = 0; h < 4; h++) {
        int c = tid + h * 256;
        int row = c >> 3, seg = c & 7;
        uint32_t dst = abase + (uint32_t)(row * PADK + seg * 8) * 2;
        CP16(dst, Ap + (size_t)(bm + row) * DD + ko + seg * 8);
    }
    // B: 256 rows x 128 B = 2048 x 16B chunks (8/thread)
#pragma unroll
    for (int h = 0; h < 8; h++) {
        int c = tid + h * 256;
        int row = c >> 3, seg = c & 7;
        uint32_t dst = bbase + (uint32_t)(row * PADK + seg * 8) * 2;
        CP16(dst, Bp + (size_t)(bn + row) * DD + ko + seg * 8);
    }
    CP_COMMIT();
}

__global__ void __launch_bounds__(256, 1)
cosine_mma_kernel(float* __restrict__ C) {
    extern __shared__ __align__(16) __nv_bfloat16 smem[];
    const uint32_t sbase = smem_u32(smem);
    const int tid = threadIdx.x;
    const int wid = tid >> 5;
    const int lid = tid & 31;
    const int bm = blockIdx.y * BM;
    const int bn = blockIdx.x * BN;

    __shared__ float s_na[BM], s_nb[BN];
    if (tid < BM) s_na[tid] = g_na[bm + tid];
    s_nb[tid] = g_nb[bn + tid];

    const int wm = (wid >> 2) * 64;  // 2 warps along M
    const int wn = (wid & 3) * 64;   // 4 warps along N

    float acc[4][8][4];
#pragma unroll
    for (int i = 0; i < 4; i++)
#pragma unroll
        for (int j = 0; j < 8; j++)
#pragma unroll
            for (int q = 0; q < 4; q++)
                acc[i][j][q] = 0.0f;

    const int a_row = wm + ((lid >> 3) & 1) * 8 + (lid & 7);
    const int a_kof = ((lid >> 4) & 1) * 8;
    const int b_row = wn + ((lid >> 4) & 1) * 8 + (lid & 7);
    const int b_kof = ((lid >> 3) & 1) * 8;

    // prologue: stages 0, 1 in flight
    load_stage(sbase, 0, 0, bm, bn, tid);
    load_stage(sbase, 1, 1, bm, bn, tid);
    CP_WAIT(1);
    __syncthreads();

    for (int s = 0; s < SSTEPS; s++) {
        const int stage = s % STAGES;

        // issue loads for stage s+2 (slot protected by barrier at end of s-1)
        if (s + STAGES - 1 < SSTEPS)
            load_stage(sbase, (s + STAGES - 1) % STAGES, s + STAGES - 1, bm, bn, tid);

        uint32_t abase = sbase + stage * STAGE_ELEMS * 2;
        uint32_t bbase = abase + BM * PADK * 2;

#pragma unroll
        for (int k16 = 0; k16 < BK / 16; k16++) {
            const int k0 = k16 * 16;
            uint32_t a[4][4];
#pragma unroll
            for (int mi = 0; mi < 4; mi++) {
                uint32_t addr = abase + (uint32_t)((a_row + mi * 16) * PADK + k0 + a_kof) * 2;
                LDSM_X4(a[mi][0], a[mi][1], a[mi][2], a[mi][3], addr);
            }
            uint32_t b[4][4];
#pragma unroll
            for (int nj = 0; nj < 4; nj++) {
                uint32_t addr = bbase + (uint32_t)((b_row + nj * 16) * PADK + k0 + b_kof) * 2;
                LDSM_X4(b[nj][0], b[nj][1], b[nj][2], b[nj][3], addr);
            }
#pragma unroll
            for (int mi = 0; mi < 4; mi++)
#pragma unroll
                for (int ni = 0; ni < 8; ni++)
                    MMA16816(acc[mi][ni], a[mi], b[ni >> 1][(ni & 1) * 2],
                             b[ni >> 1][(ni & 1) * 2 + 1]);
        }

        CP_WAIT(1);
        __syncthreads();
    }

    // epilogue: cosine divide + store
    const int qrow = lid >> 2;
    const int qcol = (lid & 3) * 2;
#pragma unroll
    for (int mi = 0; mi < 4; mi++) {
        int m0 = wm + mi * 16 + qrow;
        float na0 = s_na[m0];
        float na1 = s_na[m0 + 8];
        float* r0 = C + (size_t)(bm + m0) * NR + bn;
        float* r1 = C + (size_t)(bm + m0 + 8) * NR + bn;
#pragma unroll
        for (int ni = 0; ni < 8; ni++) {
            int n0 = wn + ni * 8 + qcol;
            float nb0 = s_nb[n0], nb1 = s_nb[n0 + 1];
            float2 v0, v1;
            v0.x = __fdividef(acc[mi][ni][0], fmaxf(na0 * nb0, EPSV));
            v0.y = __fdividef(acc[mi][ni][1], fmaxf(na0 * nb1, EPSV));
            v1.x = __fdividef(acc[mi][ni][2], fmaxf(na1 * nb0, EPSV));
            v1.y = __fdividef(acc[mi][ni][3], fmaxf(na1 * nb1, EPSV));
            *reinterpret_cast<float2*>(r0 + n0) = v0;
            *reinterpret_cast<float2*>(r1 + n0) = v1;
        }
    }
}

// ---------------- launch ----------------
extern "C" void kernel_launch(void* const* d_in, const int* in_sizes, int n_in,
                              void* d_out, int out_size) {
    const float* x1 = (const float*)d_in[0];  // [8192, 512] -> n rows
    const float* x2 = (const float*)d_in[1];  // [8192, 512] -> m rows
    float* out = (float*)d_out;               // [8192, 8192]

    const int smem_bytes = STAGES * STAGE_ELEMS * 2;  // 165888
    cudaFuncSetAttribute(cosine_mma_kernel,
                         cudaFuncAttributeMaxDynamicSharedMemorySize, smem_bytes);

    prep_kernel<<<NR + MR, 128>>>(x1, x2);

    dim3 grid(NR / BN, MR / BM);  // (32, 64)
    cosine_mma_kernel<<<grid, 256, smem_bytes>>>(out);
}

// round 9
// speedup vs baseline: 2.8535x; 2.8535x over previous
#include <cuda_runtime.h>
#include <cuda_fp16.h>
#include <stdint.h>
#include <math.h>

#define EPSV 1e-8f
#define DD 512
#define MR 8192
#define NR 8192
#define BM 128
#define BN 128
#define BK 64            // fp16 elements per pipeline step
#define PADK 72          // padded smem row (144 B) -> conflict-free ldmatrix
#define STAGES 3
#define SSTEPS 8         // single fp16 pass: 512 / 64

// ---------------- device scratch (allocation-free) ----------------
__device__ __half g_a[(size_t)MR * DD];   // x2 as fp16
__device__ __half g_b[(size_t)NR * DD];   // x1 as fp16
__device__ float g_na[MR];
__device__ float g_nb[NR];

__device__ __forceinline__ uint32_t smem_u32(const void* p) {
    uint32_t a;
    asm("{ .reg .u64 t; cvta.to.shared.u64 t, %1; cvt.u32.u64 %0, t; }" : "=r"(a) : "l"(p));
    return a;
}

#define CP16(dst, src) \
    asm volatile("cp.async.cg.shared.global [%0], [%1], 16;" :: "r"(dst), "l"(src))
#define CP_COMMIT() asm volatile("cp.async.commit_group;" ::: "memory")
#define CP_WAIT(n)  asm volatile("cp.async.wait_group %0;" :: "n"(n) : "memory")

#define LDSM_X4(r0, r1, r2, r3, addr) \
    asm volatile("ldmatrix.sync.aligned.m8n8.x4.shared.b16 {%0,%1,%2,%3}, [%4];" \
                 : "=r"(r0), "=r"(r1), "=r"(r2), "=r"(r3) : "r"(addr))

#define MMA16816(d, a, b0, b1) \
    asm volatile("mma.sync.aligned.m16n8k16.row.col.f32.f16.f16.f32 " \
                 "{%0,%1,%2,%3}, {%4,%5,%6,%7}, {%8,%9}, {%0,%1,%2,%3};" \
                 : "+f"((d)[0]), "+f"((d)[1]), "+f"((d)[2]), "+f"((d)[3]) \
                 : "r"((a)[0]), "r"((a)[1]), "r"((a)[2]), "r"((a)[3]), "r"(b0), "r"(b1))

// ---------------- prep: fp32 -> fp16 + row norms ----------------
__global__ void prep_kernel(const float* __restrict__ x1, const float* __restrict__ x2) {
    int r = blockIdx.x;
    const float* src;
    __half* dst;
    float* nrm;
    int row;
    if (r < NR) { src = x1; dst = g_b; nrm = g_nb; row = r; }
    else        { src = x2; dst = g_a; nrm = g_na; row = r - NR; }

    const float4* p = reinterpret_cast<const float4*>(src + (size_t)row * DD);
    float4 v = p[threadIdx.x];
    float s = v.x * v.x + v.y * v.y + v.z * v.z + v.w * v.w;

    size_t o = (size_t)row * DD + threadIdx.x * 4;
    __half2 h01 = __floats2half2_rn(v.x, v.y);
    __half2 h23 = __floats2half2_rn(v.z, v.w);
    *reinterpret_cast<__half2*>(dst + o)     = h01;
    *reinterpret_cast<__half2*>(dst + o + 2) = h23;

#pragma unroll
    for (int off = 16; off > 0; off >>= 1)
        s += __shfl_down_sync(0xffffffffu, s, off);
    __shared__ float ws[4];
    if ((threadIdx.x & 31) == 0) ws[threadIdx.x >> 5] = s;
    __syncthreads();
    if (threadIdx.x == 0)
        nrm[row] = sqrtf(ws[0] + ws[1] + ws[2] + ws[3]);
}

// ---------------- GEMM via mma.sync + cosine epilogue ----------------
// Dynamic smem: STAGES stages, each [BM][PADK] A + [BN][PADK] B fp16.
#define STAGE_ELEMS ((BM + BN) * PADK)

__device__ __forceinline__ void load_stage(uint32_t sbase, int stage, int s,
                                           int bm, int bn, int tid) {
    const int ko = s * BK;
    uint32_t abase = sbase + stage * STAGE_ELEMS * 2;
    uint32_t bbase = abase + BM * PADK * 2;
    // A: 128 rows x 128 B = 1024 x 16B chunks (4/thread)
#pragma unroll
    for (int h = 0; h < 4; h++) {
        int c = tid + h * 256;
        int row = c >> 3, seg = c & 7;
        uint32_t dst = abase + (uint32_t)(row * PADK + seg * 8) * 2;
        CP16(dst, g_a + (size_t)(bm + row) * DD + ko + seg * 8);
    }
    // B: 128 rows x 128 B (4/thread)
#pragma unroll
    for (int h = 0; h < 4; h++) {
        int c = tid + h * 256;
        int row = c >> 3, seg = c & 7;
        uint32_t dst = bbase + (uint32_t)(row * PADK + seg * 8) * 2;
        CP16(dst, g_b + (size_t)(bn + row) * DD + ko + seg * 8);
    }
    CP_COMMIT();
}

__global__ void __launch_bounds__(256, 2)
cosine_mma_kernel(float* __restrict__ C) {
    extern __shared__ __align__(16) __half smem[];
    const uint32_t sbase = smem_u32(smem);
    const int tid = threadIdx.x;
    const int wid = tid >> 5;
    const int lid = tid & 31;
    const int bm = blockIdx.y * BM;
    const int bn = blockIdx.x * BN;

    __shared__ float s_na[BM], s_nb[BN];
    if (tid < BM) s_na[tid] = g_na[bm + tid];
    else s_nb[tid - BM] = g_nb[bn + tid - BM];

    const int wm = (wid & 1) * 64;   // warp m-base
    const int wn = (wid >> 1) * 32;  // warp n-base

    float acc[4][4][4];
#pragma unroll
    for (int i = 0; i < 4; i++)
#pragma unroll
        for (int j = 0; j < 4; j++)
#pragma unroll
            for (int q = 0; q < 4; q++)
                acc[i][j][q] = 0.0f;

    const int a_row = wm + ((lid >> 3) & 1) * 8 + (lid & 7);
    const int a_kof = ((lid >> 4) & 1) * 8;
    const int b_row = wn + ((lid >> 4) & 1) * 8 + (lid & 7);
    const int b_kof = ((lid >> 3) & 1) * 8;

    // prologue: stages 0, 1 in flight
    load_stage(sbase, 0, 0, bm, bn, tid);
    load_stage(sbase, 1, 1, bm, bn, tid);
    CP_WAIT(1);
    __syncthreads();

    for (int s = 0; s < SSTEPS; s++) {
        const int stage = s % STAGES;

        // issue loads for stage s+2 (slot protected by barrier at end of s-1)
        if (s + STAGES - 1 < SSTEPS)
            load_stage(sbase, (s + STAGES - 1) % STAGES, s + STAGES - 1, bm, bn, tid);

        uint32_t abase = sbase + stage * STAGE_ELEMS * 2;
        uint32_t bbase = abase + BM * PADK * 2;

#pragma unroll
        for (int k16 = 0; k16 < BK / 16; k16++) {
            const int k0 = k16 * 16;
            uint32_t a[4][4];
#pragma unroll
            for (int mi = 0; mi < 4; mi++) {
                uint32_t addr = abase + (uint32_t)((a_row + mi * 16) * PADK + k0 + a_kof) * 2;
                LDSM_X4(a[mi][0], a[mi][1], a[mi][2], a[mi][3], addr);
            }
            uint32_t b[2][4];
#pragma unroll
            for (int nj = 0; nj < 2; nj++) {
                uint32_t addr = bbase + (uint32_t)((b_row + nj * 16) * PADK + k0 + b_kof) * 2;
                LDSM_X4(b[nj][0], b[nj][1], b[nj][2], b[nj][3], addr);
            }
#pragma unroll
            for (int mi = 0; mi < 4; mi++)
#pragma unroll
                for (int ni = 0; ni < 4; ni++)
                    MMA16816(acc[mi][ni], a[mi], b[ni >> 1][(ni & 1) * 2],
                             b[ni >> 1][(ni & 1) * 2 + 1]);
        }

        CP_WAIT(1);
        __syncthreads();
    }

    // epilogue: cosine divide + store
    const int qrow = lid >> 2;
    const int qcol = (lid & 3) * 2;
#pragma unroll
    for (int mi = 0; mi < 4; mi++) {
        int m0 = wm + mi * 16 + qrow;
        float na0 = s_na[m0];
        float na1 = s_na[m0 + 8];
        float* r0 = C + (size_t)(bm + m0) * NR + bn;
        float* r1 = C + (size_t)(bm + m0 + 8) * NR + bn;
#pragma unroll
        for (int ni = 0; ni < 4; ni++) {
            int n0 = wn + ni * 8 + qcol;
            float nb0 = s_nb[n0], nb1 = s_nb[n0 + 1];
            float2 v0, v1;
            v0.x = __fdividef(acc[mi][ni][0], fmaxf(na0 * nb0, EPSV));
            v0.y = __fdividef(acc[mi][ni][1], fmaxf(na0 * nb1, EPSV));
            v1.x = __fdividef(acc[mi][ni][2], fmaxf(na1 * nb0, EPSV));
            v1.y = __fdividef(acc[mi][ni][3], fmaxf(na1 * nb1, EPSV));
            *reinterpret_cast<float2*>(r0 + n0) = v0;
            *reinterpret_cast<float2*>(r1 + n0) = v1;
        }
    }
}

// ---------------- launch ----------------
extern "C" void kernel_launch(void* const* d_in, const int* in_sizes, int n_in,
                              void* d_out, int out_size) {
    const float* x1 = (const float*)d_in[0];  // [8192, 512] -> n rows
    const float* x2 = (const float*)d_in[1];  // [8192, 512] -> m rows
    float* out = (float*)d_out;               // [8192, 8192]

    const int smem_bytes = STAGES * STAGE_ELEMS * 2;  // 110592
    cudaFuncSetAttribute(cosine_mma_kernel,
                         cudaFuncAttributeMaxDynamicSharedMemorySize, smem_bytes);

    prep_kernel<<<NR + MR, 128>>>(x1, x2);

    dim3 grid(NR / BN, MR / BM);  // (64, 64)
    cosine_mma_kernel<<<grid, 256, smem_bytes>>>(out);
}

// round 10
// speedup vs baseline: 2.9516x; 1.0344x over previous
#include <cuda_runtime.h>
#include <cuda_fp16.h>
#include <stdint.h>
#include <math.h>

#define EPSV 1e-8f
#define DD 512
#define MR 8192
#define NR 8192
#define BM 128
#define BN 128
#define BK 64            // fp16 elements per pipeline step
#define PADK 72          // padded smem row (144 B) -> conflict-free ldmatrix
#define STAGES 3
#define SSTEPS 8         // 512 / 64
#define NTHREADS 128     // 4 warps, 2x2 grid of 64x64 warp tiles

// ---------------- device scratch (allocation-free) ----------------
__device__ __half g_a[(size_t)MR * DD];   // x2 as fp16
__device__ __half g_b[(size_t)NR * DD];   // x1 as fp16
__device__ float g_na[MR];
__device__ float g_nb[NR];

__device__ __forceinline__ uint32_t smem_u32(const void* p) {
    uint32_t a;
    asm("{ .reg .u64 t; cvta.to.shared.u64 t, %1; cvt.u32.u64 %0, t; }" : "=r"(a) : "l"(p));
    return a;
}

#define CP16(dst, src) \
    asm volatile("cp.async.cg.shared.global [%0], [%1], 16;" :: "r"(dst), "l"(src))
#define CP_COMMIT() asm volatile("cp.async.commit_group;" ::: "memory")
#define CP_WAIT(n)  asm volatile("cp.async.wait_group %0;" :: "n"(n) : "memory")

#define LDSM_X4(r0, r1, r2, r3, addr) \
    asm volatile("ldmatrix.sync.aligned.m8n8.x4.shared.b16 {%0,%1,%2,%3}, [%4];" \
                 : "=r"(r0), "=r"(r1), "=r"(r2), "=r"(r3) : "r"(addr))

#define MMA16816(d, a, b0, b1) \
    asm volatile("mma.sync.aligned.m16n8k16.row.col.f32.f16.f16.f32 " \
                 "{%0,%1,%2,%3}, {%4,%5,%6,%7}, {%8,%9}, {%0,%1,%2,%3};" \
                 : "+f"((d)[0]), "+f"((d)[1]), "+f"((d)[2]), "+f"((d)[3]) \
                 : "r"((a)[0]), "r"((a)[1]), "r"((a)[2]), "r"((a)[3]), "r"(b0), "r"(b1))

// ---------------- prep: fp32 -> fp16 + row norms ----------------
__global__ void prep_kernel(const float* __restrict__ x1, const float* __restrict__ x2) {
    int r = blockIdx.x;
    const float* src;
    __half* dst;
    float* nrm;
    int row;
    if (r < NR) { src = x1; dst = g_b; nrm = g_nb; row = r; }
    else        { src = x2; dst = g_a; nrm = g_na; row = r - NR; }

    const float4* p = reinterpret_cast<const float4*>(src + (size_t)row * DD);
    float4 v = p[threadIdx.x];
    float s = v.x * v.x + v.y * v.y + v.z * v.z + v.w * v.w;

    size_t o = (size_t)row * DD + threadIdx.x * 4;
    *reinterpret_cast<__half2*>(dst + o)     = __floats2half2_rn(v.x, v.y);
    *reinterpret_cast<__half2*>(dst + o + 2) = __floats2half2_rn(v.z, v.w);

#pragma unroll
    for (int off = 16; off > 0; off >>= 1)
        s += __shfl_down_sync(0xffffffffu, s, off);
    __shared__ float ws[4];
    if ((threadIdx.x & 31) == 0) ws[threadIdx.x >> 5] = s;
    __syncthreads();
    if (threadIdx.x == 0)
        nrm[row] = sqrtf(ws[0] + ws[1] + ws[2] + ws[3]);
}

// ---------------- GEMM via mma.sync + cosine epilogue ----------------
#define STAGE_ELEMS ((BM + BN) * PADK)

__device__ __forceinline__ void load_stage(uint32_t sbase, int stage, int s,
                                           int bm, int bn, int tid) {
    const int ko = s * BK;
    uint32_t abase = sbase + stage * STAGE_ELEMS * 2;
    uint32_t bbase = abase + BM * PADK * 2;
    // A: 128 rows x 128 B = 1024 x 16B chunks (8/thread at 128 threads)
#pragma unroll
    for (int h = 0; h < 8; h++) {
        int c = tid + h * NTHREADS;
        int row = c >> 3, seg = c & 7;
        uint32_t dst = abase + (uint32_t)(row * PADK + seg * 8) * 2;
        CP16(dst, g_a + (size_t)(bm + row) * DD + ko + seg * 8);
    }
    // B: 128 rows x 128 B (8/thread)
#pragma unroll
    for (int h = 0; h < 8; h++) {
        int c = tid + h * NTHREADS;
        int row = c >> 3, seg = c & 7;
        uint32_t dst = bbase + (uint32_t)(row * PADK + seg * 8) * 2;
        CP16(dst, g_b + (size_t)(bn + row) * DD + ko + seg * 8);
    }
    CP_COMMIT();
}

__global__ void __launch_bounds__(NTHREADS, 2)
cosine_mma_kernel(float* __restrict__ C) {
    extern __shared__ __align__(16) __half smem[];
    const uint32_t sbase = smem_u32(smem);
    const int tid = threadIdx.x;
    const int wid = tid >> 5;
    const int lid = tid & 31;
    const int bm = blockIdx.y * BM;
    const int bn = blockIdx.x * BN;

    __shared__ float s_na[BM], s_nb[BN];
    s_na[tid] = g_na[bm + tid];
    s_nb[tid] = g_nb[bn + tid];

    const int wm = (wid & 1) * 64;   // 2 warps along M
    const int wn = (wid >> 1) * 64;  // 2 warps along N

    float acc[4][8][4];
#pragma unroll
    for (int i = 0; i < 4; i++)
#pragma unroll
        for (int j = 0; j < 8; j++)
#pragma unroll
            for (int q = 0; q < 4; q++)
                acc[i][j][q] = 0.0f;

    const int a_row = wm + ((lid >> 3) & 1) * 8 + (lid & 7);
    const int a_kof = ((lid >> 4) & 1) * 8;
    const int b_row = wn + ((lid >> 4) & 1) * 8 + (lid & 7);
    const int b_kof = ((lid >> 3) & 1) * 8;

    // prologue: stages 0, 1 in flight
    load_stage(sbase, 0, 0, bm, bn, tid);
    load_stage(sbase, 1, 1, bm, bn, tid);
    CP_WAIT(1);
    __syncthreads();

    for (int s = 0; s < SSTEPS; s++) {
        const int stage = s % STAGES;

        // issue loads for stage s+2 (slot protected by barrier at end of s-1)
        if (s + STAGES - 1 < SSTEPS)
            load_stage(sbase, (s + STAGES - 1) % STAGES, s + STAGES - 1, bm, bn, tid);

        uint32_t abase = sbase + stage * STAGE_ELEMS * 2;
        uint32_t bbase = abase + BM * PADK * 2;

#pragma unroll
        for (int k16 = 0; k16 < BK / 16; k16++) {
            const int k0 = k16 * 16;
            uint32_t a[4][4];
#pragma unroll
            for (int mi = 0; mi < 4; mi++) {
                uint32_t addr = abase + (uint32_t)((a_row + mi * 16) * PADK + k0 + a_kof) * 2;
                LDSM_X4(a[mi][0], a[mi][1], a[mi][2], a[mi][3], addr);
            }
            uint32_t b[4][4];
#pragma unroll
            for (int nj = 0; nj < 4; nj++) {
                uint32_t addr = bbase + (uint32_t)((b_row + nj * 16) * PADK + k0 + b_kof) * 2;
                LDSM_X4(b[nj][0], b[nj][1], b[nj][2], b[nj][3], addr);
            }
#pragma unroll
            for (int mi = 0; mi < 4; mi++)
#pragma unroll
                for (int ni = 0; ni < 8; ni++)
                    MMA16816(acc[mi][ni], a[mi], b[ni >> 1][(ni & 1) * 2],
                             b[ni >> 1][(ni & 1) * 2 + 1]);
        }

        CP_WAIT(1);
        __syncthreads();
    }

    // epilogue: cosine divide + store
    const int qrow = lid >> 2;
    const int qcol = (lid & 3) * 2;
#pragma unroll
    for (int mi = 0; mi < 4; mi++) {
        int m0 = wm + mi * 16 + qrow;
        float na0 = s_na[m0];
        float na1 = s_na[m0 + 8];
        float* r0 = C + (size_t)(bm + m0) * NR + bn;
        float* r1 = C + (size_t)(bm + m0 + 8) * NR + bn;
#pragma unroll
        for (int ni = 0; ni < 8; ni++) {
            int n0 = wn + ni * 8 + qcol;
            float nb0 = s_nb[n0], nb1 = s_nb[n0 + 1];
            float2 v0, v1;
            v0.x = __fdividef(acc[mi][ni][0], fmaxf(na0 * nb0, EPSV));
            v0.y = __fdividef(acc[mi][ni][1], fmaxf(na0 * nb1, EPSV));
            v1.x = __fdividef(acc[mi][ni][2], fmaxf(na1 * nb0, EPSV));
            v1.y = __fdividef(acc[mi][ni][3], fmaxf(na1 * nb1, EPSV));
            *reinterpret_cast<float2*>(r0 + n0) = v0;
            *reinterpret_cast<float2*>(r1 + n0) = v1;
        }
    }
}

// ---------------- launch ----------------
extern "C" void kernel_launch(void* const* d_in, const int* in_sizes, int n_in,
                              void* d_out, int out_size) {
    const float* x1 = (const float*)d_in[0];  // [8192, 512] -> n rows
    const float* x2 = (const float*)d_in[1];  // [8192, 512] -> m rows
    float* out = (float*)d_out;               // [8192, 8192]

    const int smem_bytes = STAGES * STAGE_ELEMS * 2;  // 110592
    cudaFuncSetAttribute(cosine_mma_kernel,
                         cudaFuncAttributeMaxDynamicSharedMemorySize, smem_bytes);

    prep_kernel<<<NR + MR, 128>>>(x1, x2);

    dim3 grid(NR / BN, MR / BM);  // (64, 64)
    cosine_mma_kernel<<<grid, NTHREADS, smem_bytes>>>(out);
}